// round 8
// baseline (speedup 1.0000x reference)
#include <cuda_runtime.h>

// Fused upsample2x-bilinear -> affine_grid -> grid_sample_bilinear.
// Separable composition: output = 3x3 weighted sum over ORIGINAL image.
// R8: R7 (NHWC, lane-quad channels, SHFL tap broadcast) + PTX-predicated
// tap loads (zero-weight taps issue no memory request: E[taps]=6.25 of 9)
// + STG.128 epilogue.

#define N_   8
#define C_   32
#define HI   256
#define WI   256
#define HU   512
#define WU   512

// NHWC scratch: 8*256*256*32 floats = 67 MB (device global: allocation-free)
__device__ float4 g_nhwc4[N_ * HI * WI * (C_ / 4)];

// ---------------- prepass: NCHW -> NHWC tiled transpose ----------------
__global__ void __launch_bounds__(256)
transpose_nhwc(const float* __restrict__ x) {
    __shared__ float t[C_][33];
    int lane = threadIdx.x & 31;
    int wp   = threadIdx.x >> 5;          // 8 warps
    int bh = blockIdx.x;                   // n*HI + h
    int w0 = blockIdx.y << 5;              // w tile origin (8 tiles)
    int n = bh >> 8, h = bh & 255;

    const float* ip = x + (((long long)n * C_) * HI + h) * WI + w0;
    #pragma unroll
    for (int k = 0; k < 4; k++) {
        int c = (k << 3) + wp;
        t[c][lane] = ip[(long long)c * (HI * WI) + lane];   // coalesced read
    }
    __syncthreads();

    float* op = (float*)g_nhwc4 + (((long long)n * HI + h) * WI + w0) * C_;
    #pragma unroll
    for (int k = 0; k < 4; k++) {
        int wl = (k << 3) + wp;
        op[wl * C_ + lane] = t[lane][wl];                   // coalesced write
    }
}

// ---------------- main fused kernel ----------------
__device__ __forceinline__ void axis_taps(float f, int U, int O,
                                          int& base, float w[3]) {
    float f0 = floorf(f);
    int   i0 = (int)f0;
    float wf = f - f0;

    w[0] = 0.f; w[1] = 0.f; w[2] = 0.f;
    base = 0;

    #pragma unroll
    for (int k = 0; k < 2; k++) {
        int   t  = i0 + k;
        float Wk = (k == 0) ? (1.0f - wf) : wf;
        Wk = (t >= 0 && t < U) ? Wk : 0.0f;          // zero-padding validity
        int tc = min(max(t, 0), U - 1);
        float s  = fmaxf((float)tc * 0.5f - 0.25f, 0.0f);  // upsample source
        int   o0 = (int)s;
        float wu = s - (float)o0;
        int   o1 = min(o0 + 1, O - 1);
        if (k == 0) base = o0;                       // taps are monotone
        w[o0 - base] += Wk * (1.0f - wu);
        w[o1 - base] += Wk * wu;
    }
}

// Predicated tap: skip load+fma entirely when w == 0 (no memory request,
// no BSSY/BSYNC). Bit-exact: fma(0, v, acc) == acc for finite v.
__device__ __forceinline__ void tap_fma(float4& acc, const float4* addr, float w) {
    asm("{\n\t"
        ".reg .pred p;\n\t"
        ".reg .f32 t0, t1, t2, t3;\n\t"
        "setp.ne.f32 p, %4, 0f00000000;\n\t"
        "@p ld.global.nc.v4.f32 {t0, t1, t2, t3}, [%5];\n\t"
        "@p fma.rn.f32 %0, t0, %4, %0;\n\t"
        "@p fma.rn.f32 %1, t1, %4, %1;\n\t"
        "@p fma.rn.f32 %2, t2, %4, %2;\n\t"
        "@p fma.rn.f32 %3, t3, %4, %3;\n\t"
        "}"
        : "+f"(acc.x), "+f"(acc.y), "+f"(acc.z), "+f"(acc.w)
        : "f"(w), "l"((const void*)addr));
}

__global__ void __launch_bounds__(256)
fused_gather_nhwc(const float* __restrict__ theta,
                  float* __restrict__ out) {
    __shared__ float obuf[8][C_][33];   // [warp][channel][point], pad 33

    const unsigned FULL = 0xFFFFFFFFu;
    int w    = threadIdx.x >> 5;
    int lane = threadIdx.x & 31;
    int wid  = blockIdx.x * 8 + w;
    int n   = wid >> 13;                 // 8192 warps per image
    int r   = wid & 8191;
    int yo  = r >> 4;                    // 512 rows
    int xo0 = (r & 15) << 5;             // 16 x-segments of 32

    float* outp = out + ((long long)n * C_) * (HU * WU)
                      + (long long)yo * WU + xo0;

    // ---- per-lane taps for point (xo0+lane, yo) ----
    int ro4[3], co4[3];
    float wy[3], wx[3];
    int z;                               // 1 if this point contributes zero
    {
        int xo = xo0 + lane;
        float gxn = (2.0f * (float)xo + 1.0f) / (float)WU - 1.0f;
        float gyn = (2.0f * (float)yo + 1.0f) / (float)HU - 1.0f;
        const float* th = theta + n * 6;
        float gox = __ldg(th + 0) * gxn + __ldg(th + 1) * gyn + __ldg(th + 2);
        float goy = __ldg(th + 3) * gxn + __ldg(th + 4) * gyn + __ldg(th + 5);
        float ix = ((gox + 1.0f) * (float)WU - 1.0f) * 0.5f;
        float iy = ((goy + 1.0f) * (float)HU - 1.0f) * 0.5f;

        int by, bx;
        axis_taps(iy, HU, HI, by, wy);   // indices always clamped into range
        axis_taps(ix, WU, WI, bx, wx);

        #pragma unroll
        for (int i = 0; i < 3; i++) {
            ro4[i] = min(by + i, HI - 1) * (WI * (C_ / 4));  // float4 units
            co4[i] = min(bx + i, WI - 1) * (C_ / 4);
        }
        z = ((wy[0] + wy[1] + wy[2]) == 0.0f) ||
            ((wx[0] + wx[1] + wx[2]) == 0.0f);
    }

    // ---- whole warp out of bounds: direct zero stores (STG.128) ----
    if (__all_sync(FULL, z)) {
        float4 zv = make_float4(0.f, 0.f, 0.f, 0.f);
        #pragma unroll
        for (int k = 0; k < 8; k++) {
            int c = (k << 2) | (lane >> 3);
            int piece = lane & 7;
            *(float4*)(outp + (long long)c * (HU * WU) + (piece << 2)) = zv;
        }
        return;
    }

    // ---- 8 passes of 4 points x 32 channels ----
    int g  = lane >> 3;                  // point within pass
    int lc = lane & 7;                   // channel quad
    const float4* xp = g_nhwc4 + (long long)n * (HI * WI * (C_ / 4)) + lc;

    #pragma unroll 2
    for (int pass = 0; pass < 8; pass++) {
        int src = (pass << 2) | g;
        int R0 = __shfl_sync(FULL, ro4[0], src);
        int R1 = __shfl_sync(FULL, ro4[1], src);
        int R2 = __shfl_sync(FULL, ro4[2], src);
        int K0 = __shfl_sync(FULL, co4[0], src);
        int K1 = __shfl_sync(FULL, co4[1], src);
        int K2 = __shfl_sync(FULL, co4[2], src);
        float Y0 = __shfl_sync(FULL, wy[0], src);
        float Y1 = __shfl_sync(FULL, wy[1], src);
        float Y2 = __shfl_sync(FULL, wy[2], src);
        float X0 = __shfl_sync(FULL, wx[0], src);
        float X1 = __shfl_sync(FULL, wx[1], src);
        float X2 = __shfl_sync(FULL, wx[2], src);

        float4 acc = make_float4(0.f, 0.f, 0.f, 0.f);
        {
            int   Rs[3] = {R0, R1, R2};
            int   Ks[3] = {K0, K1, K2};
            float Ys[3] = {Y0, Y1, Y2};
            float Xs[3] = {X0, X1, X2};
            #pragma unroll
            for (int i = 0; i < 3; i++)
                #pragma unroll
                for (int jj = 0; jj < 3; jj++)
                    tap_fma(acc, xp + Rs[i] + Ks[jj], Ys[i] * Xs[jj]);
        }

        int p  = (pass << 2) | g;
        int cb = lc << 2;
        obuf[w][cb + 0][p] = acc.x;      // bank = (4lc+g)+const: conflict-free
        obuf[w][cb + 1][p] = acc.y;
        obuf[w][cb + 2][p] = acc.z;
        obuf[w][cb + 3][p] = acc.w;
    }
    __syncwarp();

    // ---- NCHW stores: 8 x STG.128 (4 channel-rows / instruction) ----
    #pragma unroll
    for (int k = 0; k < 8; k++) {
        int c = (k << 2) | (lane >> 3);
        int piece = lane & 7;
        float4 v;
        v.x = obuf[w][c][(piece << 2) + 0];   // (c + 4p + q) mod 32 distinct
        v.y = obuf[w][c][(piece << 2) + 1];
        v.z = obuf[w][c][(piece << 2) + 2];
        v.w = obuf[w][c][(piece << 2) + 3];
        *(float4*)(outp + (long long)c * (HU * WU) + (piece << 2)) = v;
    }
}

extern "C" void kernel_launch(void* const* d_in, const int* in_sizes, int n_in,
                              void* d_out, int out_size) {
    const float* x     = (const float*)d_in[0];
    const float* theta = (const float*)d_in[1];
    float*       out   = (float*)d_out;

    dim3 tg(N_ * HI, WI / 32);           // (2048, 8) tiles of 32c x 32w
    transpose_nhwc<<<tg, 256>>>(x);

    // 65536 warps: one warp per 32-point output row segment (all 32 channels)
    fused_gather_nhwc<<<8192, 256>>>(theta, out);
}

// round 9
// speedup vs baseline: 1.1504x; 1.1504x over previous
#include <cuda_runtime.h>

// Fused upsample2x-bilinear -> affine_grid -> grid_sample_bilinear.
// Separable composition: output = 3x3 weighted sum over ORIGINAL image.
// R9: R8's predicated tap-skip, restructured for MLP: 9 predicated loads
// into zero-init temps issued back-to-back, then unconditional FMAs.

#define N_   8
#define C_   32
#define HI   256
#define WI   256
#define HU   512
#define WU   512

// NHWC scratch: 8*256*256*32 floats = 67 MB (device global: allocation-free)
__device__ float4 g_nhwc4[N_ * HI * WI * (C_ / 4)];

// ---------------- prepass: NCHW -> NHWC tiled transpose ----------------
__global__ void __launch_bounds__(256)
transpose_nhwc(const float* __restrict__ x) {
    __shared__ float t[C_][33];
    int lane = threadIdx.x & 31;
    int wp   = threadIdx.x >> 5;          // 8 warps
    int bh = blockIdx.x;                   // n*HI + h
    int w0 = blockIdx.y << 5;              // w tile origin (8 tiles)
    int n = bh >> 8, h = bh & 255;

    const float* ip = x + (((long long)n * C_) * HI + h) * WI + w0;
    #pragma unroll
    for (int k = 0; k < 4; k++) {
        int c = (k << 3) + wp;
        t[c][lane] = ip[(long long)c * (HI * WI) + lane];   // coalesced read
    }
    __syncthreads();

    float* op = (float*)g_nhwc4 + (((long long)n * HI + h) * WI + w0) * C_;
    #pragma unroll
    for (int k = 0; k < 4; k++) {
        int wl = (k << 3) + wp;
        op[wl * C_ + lane] = t[lane][wl];                   // coalesced write
    }
}

// ---------------- main fused kernel ----------------
__device__ __forceinline__ void axis_taps(float f, int U, int O,
                                          int& base, float w[3]) {
    float f0 = floorf(f);
    int   i0 = (int)f0;
    float wf = f - f0;

    w[0] = 0.f; w[1] = 0.f; w[2] = 0.f;
    base = 0;

    #pragma unroll
    for (int k = 0; k < 2; k++) {
        int   t  = i0 + k;
        float Wk = (k == 0) ? (1.0f - wf) : wf;
        Wk = (t >= 0 && t < U) ? Wk : 0.0f;          // zero-padding validity
        int tc = min(max(t, 0), U - 1);
        float s  = fmaxf((float)tc * 0.5f - 0.25f, 0.0f);  // upsample source
        int   o0 = (int)s;
        float wu = s - (float)o0;
        int   o1 = min(o0 + 1, O - 1);
        if (k == 0) base = o0;                       // taps are monotone
        w[o0 - base] += Wk * (1.0f - wu);
        w[o1 - base] += Wk * wu;
    }
}

// Predicated load into zero-initialized temp: no memory request when w == 0.
// FMA is done unconditionally by the caller (fma(0,0,acc)... w*0 exact).
__device__ __forceinline__ void pred_load(float4& t, const float4* addr, float w) {
    asm("{\n\t"
        ".reg .pred p;\n\t"
        "setp.ne.f32 p, %4, 0f00000000;\n\t"
        "mov.f32 %0, 0f00000000;\n\t"
        "mov.f32 %1, 0f00000000;\n\t"
        "mov.f32 %2, 0f00000000;\n\t"
        "mov.f32 %3, 0f00000000;\n\t"
        "@p ld.global.nc.v4.f32 {%0, %1, %2, %3}, [%5];\n\t"
        "}"
        : "=f"(t.x), "=f"(t.y), "=f"(t.z), "=f"(t.w)
        : "f"(w), "l"((const void*)addr));
}

__global__ void __launch_bounds__(256, 3)
fused_gather_nhwc(const float* __restrict__ theta,
                  float* __restrict__ out) {
    __shared__ float obuf[8][C_][33];   // [warp][channel][point], pad 33

    const unsigned FULL = 0xFFFFFFFFu;
    int w    = threadIdx.x >> 5;
    int lane = threadIdx.x & 31;
    int wid  = blockIdx.x * 8 + w;
    int n   = wid >> 13;                 // 8192 warps per image
    int r   = wid & 8191;
    int yo  = r >> 4;                    // 512 rows
    int xo0 = (r & 15) << 5;             // 16 x-segments of 32

    float* outp = out + ((long long)n * C_) * (HU * WU)
                      + (long long)yo * WU + xo0;

    // ---- per-lane taps for point (xo0+lane, yo) ----
    int ro4[3], co4[3];
    float wy[3], wx[3];
    int z;                               // 1 if this point contributes zero
    {
        int xo = xo0 + lane;
        float gxn = (2.0f * (float)xo + 1.0f) / (float)WU - 1.0f;
        float gyn = (2.0f * (float)yo + 1.0f) / (float)HU - 1.0f;
        const float* th = theta + n * 6;
        float gox = __ldg(th + 0) * gxn + __ldg(th + 1) * gyn + __ldg(th + 2);
        float goy = __ldg(th + 3) * gxn + __ldg(th + 4) * gyn + __ldg(th + 5);
        float ix = ((gox + 1.0f) * (float)WU - 1.0f) * 0.5f;
        float iy = ((goy + 1.0f) * (float)HU - 1.0f) * 0.5f;

        int by, bx;
        axis_taps(iy, HU, HI, by, wy);   // indices always clamped into range
        axis_taps(ix, WU, WI, bx, wx);

        #pragma unroll
        for (int i = 0; i < 3; i++) {
            ro4[i] = min(by + i, HI - 1) * (WI * (C_ / 4));  // float4 units
            co4[i] = min(bx + i, WI - 1) * (C_ / 4);
        }
        z = ((wy[0] + wy[1] + wy[2]) == 0.0f) ||
            ((wx[0] + wx[1] + wx[2]) == 0.0f);
    }

    // ---- whole warp out of bounds: direct zero stores (STG.128) ----
    if (__all_sync(FULL, z)) {
        float4 zv = make_float4(0.f, 0.f, 0.f, 0.f);
        #pragma unroll
        for (int k = 0; k < 8; k++) {
            int c = (k << 2) | (lane >> 3);
            int piece = lane & 7;
            *(float4*)(outp + (long long)c * (HU * WU) + (piece << 2)) = zv;
        }
        return;
    }

    // ---- 8 passes of 4 points x 32 channels ----
    int g  = lane >> 3;                  // point within pass
    int lc = lane & 7;                   // channel quad
    const float4* xp = g_nhwc4 + (long long)n * (HI * WI * (C_ / 4)) + lc;

    for (int pass = 0; pass < 8; pass++) {
        int src = (pass << 2) | g;
        int R0 = __shfl_sync(FULL, ro4[0], src);
        int R1 = __shfl_sync(FULL, ro4[1], src);
        int R2 = __shfl_sync(FULL, ro4[2], src);
        int K0 = __shfl_sync(FULL, co4[0], src);
        int K1 = __shfl_sync(FULL, co4[1], src);
        int K2 = __shfl_sync(FULL, co4[2], src);
        float Y0 = __shfl_sync(FULL, wy[0], src);
        float Y1 = __shfl_sync(FULL, wy[1], src);
        float Y2 = __shfl_sync(FULL, wy[2], src);
        float X0 = __shfl_sync(FULL, wx[0], src);
        float X1 = __shfl_sync(FULL, wx[1], src);
        float X2 = __shfl_sync(FULL, wx[2], src);

        float wij[9];
        wij[0] = Y0 * X0; wij[1] = Y0 * X1; wij[2] = Y0 * X2;
        wij[3] = Y1 * X0; wij[4] = Y1 * X1; wij[5] = Y1 * X2;
        wij[6] = Y2 * X0; wij[7] = Y2 * X1; wij[8] = Y2 * X2;

        // 9 predicated loads issued back-to-back (high MLP)
        float4 t[9];
        pred_load(t[0], xp + R0 + K0, wij[0]);
        pred_load(t[1], xp + R0 + K1, wij[1]);
        pred_load(t[2], xp + R0 + K2, wij[2]);
        pred_load(t[3], xp + R1 + K0, wij[3]);
        pred_load(t[4], xp + R1 + K1, wij[4]);
        pred_load(t[5], xp + R1 + K2, wij[5]);
        pred_load(t[6], xp + R2 + K0, wij[6]);
        pred_load(t[7], xp + R2 + K1, wij[7]);
        pred_load(t[8], xp + R2 + K2, wij[8]);

        float4 acc = make_float4(0.f, 0.f, 0.f, 0.f);
        #pragma unroll
        for (int k = 0; k < 9; k++) {
            acc.x = fmaf(wij[k], t[k].x, acc.x);
            acc.y = fmaf(wij[k], t[k].y, acc.y);
            acc.z = fmaf(wij[k], t[k].z, acc.z);
            acc.w = fmaf(wij[k], t[k].w, acc.w);
        }

        int p  = (pass << 2) | g;
        int cb = lc << 2;
        obuf[w][cb + 0][p] = acc.x;      // bank = (4lc+g)+const: conflict-free
        obuf[w][cb + 1][p] = acc.y;
        obuf[w][cb + 2][p] = acc.z;
        obuf[w][cb + 3][p] = acc.w;
    }
    __syncwarp();

    // ---- NCHW stores: 8 x STG.128 (4 channel-rows / instruction) ----
    #pragma unroll
    for (int k = 0; k < 8; k++) {
        int c = (k << 2) | (lane >> 3);
        int piece = lane & 7;
        float4 v;
        v.x = obuf[w][c][(piece << 2) + 0];   // banks distinct across lanes
        v.y = obuf[w][c][(piece << 2) + 1];
        v.z = obuf[w][c][(piece << 2) + 2];
        v.w = obuf[w][c][(piece << 2) + 3];
        *(float4*)(outp + (long long)c * (HU * WU) + (piece << 2)) = v;
    }
}

extern "C" void kernel_launch(void* const* d_in, const int* in_sizes, int n_in,
                              void* d_out, int out_size) {
    const float* x     = (const float*)d_in[0];
    const float* theta = (const float*)d_in[1];
    float*       out   = (float*)d_out;

    dim3 tg(N_ * HI, WI / 32);           // (2048, 8) tiles of 32c x 32w
    transpose_nhwc<<<tg, 256>>>(x);

    // 65536 warps: one warp per 32-point output row segment (all 32 channels)
    fused_gather_nhwc<<<8192, 256>>>(theta, out);
}